// round 1
// baseline (speedup 1.0000x reference)
#include <cuda_runtime.h>
#include <math.h>
#include <stdint.h>

#define BATCH 8
#define SEQ   2048
#define NBL   (BATCH*SEQ)          // 16384
#define DM    512
#define DIN   1024
#define NH    16
#define HD    64
#define DS    64
#define CONVD 1152
#define DPROJ 2192
#define DFF   2048
#define EPSR  1e-6f

// -------- scratch (static device allocations; no cudaMalloc allowed) --------
static __device__ float g_u[(size_t)NBL*DM];        // rmsnorm(x*mask); later reused for h
static __device__ float g_zx[(size_t)NBL*DPROJ];    // in-proj output
static __device__ float g_xbc[(size_t)NBL*CONVD];   // conv+silu output
static __device__ float g_y[(size_t)NBL*DIN];       // scan accumulation
static __device__ float g_y2[(size_t)NBL*DIN];      // gated-normed y
static __device__ float g_ff[(size_t)NBL*DFF];      // gelu(h@W1+b1)

// -------- math helpers --------
__device__ __forceinline__ float siluf(float x){ return x / (1.f + expf(-x)); }
__device__ __forceinline__ float geluf(float x){
    // jax.nn.gelu default (approximate=True): tanh formulation
    float x3 = x*x*x;
    return 0.5f*x*(1.f + tanhf(0.7978845608028654f*(x + 0.044715f*x3)));
}
__device__ __forceinline__ float softplusf(float x){
    return fmaxf(x, 0.f) + log1pf(expf(-fabsf(x)));
}

// -------- u = rmsnorm(x * mask), rows of 512, 128 threads --------
__global__ void __launch_bounds__(128) prenorm_kernel(const float* __restrict__ x,
                                                      const float* __restrict__ mask,
                                                      float* __restrict__ u){
    int row = blockIdx.x;
    int t = threadIdx.x;
    float mk = mask[row];
    float4 a = ((const float4*)(x + (size_t)row*DM))[t];
    a.x*=mk; a.y*=mk; a.z*=mk; a.w*=mk;
    float ss = a.x*a.x + a.y*a.y + a.z*a.z + a.w*a.w;
    __shared__ float sh[4];
    #pragma unroll
    for (int o=16;o;o>>=1) ss += __shfl_xor_sync(0xffffffffu, ss, o);
    if ((t&31)==0) sh[t>>5] = ss;
    __syncthreads();
    float tot = sh[0]+sh[1]+sh[2]+sh[3];
    float inv = rsqrtf(tot*(1.f/DM) + EPSR);
    float4 o4 = make_float4(a.x*inv, a.y*inv, a.z*inv, a.w*inv);
    ((float4*)(u + (size_t)row*DM))[t] = o4;
}

// -------- generic tiled SGEMM: C[M,N] = A[M,K] @ B[K,N] (row-major) --------
// MODE 0: plain store, MODE 1: gelu(acc+bias), MODE 2: acc + bias + 2*res
template<int MODE>
__global__ void __launch_bounds__(256) sgemm_kernel(const float* __restrict__ A,
                                                    const float* __restrict__ B,
                                                    float* __restrict__ C,
                                                    int M, int N, int K,
                                                    const float* __restrict__ bias,
                                                    const float* __restrict__ res){
    __shared__ float As[8][128];
    __shared__ float Bs[8][128];
    const int tid = threadIdx.x;
    const int tx = tid & 15;        // n-dir (16)
    const int ty = tid >> 4;        // m-dir (16)
    const int aRow = tid >> 1;      // 0..127
    const int aCol = (tid & 1) << 2;
    const int bRow = tid >> 5;      // 0..7
    const int bCol = (tid & 31) << 2;
    const int bColG = blockIdx.x*128 + bCol;
    const float* Ap = A + (size_t)(blockIdx.y*128 + aRow)*K + aCol;
    float acc[8][8];
    #pragma unroll
    for (int i=0;i<8;i++)
        #pragma unroll
        for (int j=0;j<8;j++) acc[i][j]=0.f;

    for (int k0=0; k0<K; k0+=8){
        float4 av = *(const float4*)(Ap + k0);
        As[aCol+0][aRow]=av.x; As[aCol+1][aRow]=av.y;
        As[aCol+2][aRow]=av.z; As[aCol+3][aRow]=av.w;
        const float* Bp = B + (size_t)(k0+bRow)*N;
        float4 bv;
        if (bColG + 3 < N) bv = *(const float4*)(Bp + bColG);
        else {
            bv.x = (bColG+0<N)?Bp[bColG+0]:0.f;
            bv.y = (bColG+1<N)?Bp[bColG+1]:0.f;
            bv.z = (bColG+2<N)?Bp[bColG+2]:0.f;
            bv.w = 0.f;
        }
        *(float4*)&Bs[bRow][bCol] = bv;
        __syncthreads();
        #pragma unroll
        for (int kk=0;kk<8;kk++){
            float ar[8], br[8];
            *(float4*)(ar)   = *(const float4*)&As[kk][ty*8];
            *(float4*)(ar+4) = *(const float4*)&As[kk][ty*8+4];
            *(float4*)(br)   = *(const float4*)&Bs[kk][tx*8];
            *(float4*)(br+4) = *(const float4*)&Bs[kk][tx*8+4];
            #pragma unroll
            for (int i=0;i<8;i++)
                #pragma unroll
                for (int j=0;j<8;j++)
                    acc[i][j] = fmaf(ar[i], br[j], acc[i][j]);
        }
        __syncthreads();
    }
    const int row0 = blockIdx.y*128 + ty*8;
    const int col0 = blockIdx.x*128 + tx*8;
    #pragma unroll
    for (int i=0;i<8;i++){
        size_t rb = (size_t)(row0+i)*N;
        #pragma unroll
        for (int j=0;j<8;j++){
            int c = col0 + j;
            if (c < N){
                float v = acc[i][j];
                if (MODE==1) v = geluf(v + bias[c]);
                if (MODE==2) v = v + bias[c] + 2.f*res[rb + c];
                C[rb + c] = v;
            }
        }
    }
}

// -------- depthwise causal conv(K=4) + bias + silu + mask --------
__global__ void conv_kernel(const float* __restrict__ cw, const float* __restrict__ cb,
                            const float* __restrict__ mask){
    long idx = (long)blockIdx.x*blockDim.x + threadIdx.x;
    if (idx >= (long)NBL*CONVD) return;
    int c = (int)(idx % CONVD);
    long bl = idx / CONVD;
    int l = (int)(bl % SEQ);
    float acc = cb[c];
    #pragma unroll
    for (int i=0;i<4;i++){
        int ls = l + i - 3;
        if (ls >= 0)
            acc += g_zx[(size_t)(bl + (i-3))*DPROJ + DIN + c] * cw[c*4 + i];
    }
    g_xbc[idx] = siluf(acc) * mask[bl];
}

// -------- dt = softplus(dt_raw + dt_bias) -> output region (also scan input) ----
__global__ void dt_kernel(const float* __restrict__ dt_bias, float* __restrict__ out_dt){
    int idx = blockIdx.x*blockDim.x + threadIdx.x;
    if (idx >= NBL*NH) return;
    int hh = idx & (NH-1);
    long bl = idx >> 4;
    float v = g_zx[(size_t)bl*DPROJ + (DIN+CONVD) + hh] + dt_bias[hh];
    out_dt[idx] = softplusf(v);
}

// -------- z copy to output (raw, pre-silu) --------
__global__ void zcopy_kernel(float* __restrict__ out_z){
    int idx = blockIdx.x*blockDim.x + threadIdx.x;   // NBL*256 float4s
    if (idx >= NBL*(DIN/4)) return;
    long bl = idx >> 8; int c4 = idx & 255;
    ((float4*)out_z)[idx] = *(const float4*)&g_zx[(size_t)bl*DPROJ + c4*4];
}

__global__ void zero_y_kernel(){
    long i = (long)blockIdx.x*blockDim.x + threadIdx.x;
    if (i < (long)NBL*DIN/4) ((float4*)g_y)[i] = make_float4(0.f,0.f,0.f,0.f);
}

// -------- bidirectional SSM scan --------
// grid (2, NH, BATCH), 64 threads. Thread p keeps state row h[p][0..63] in regs.
#define CT 32
__global__ void __launch_bounds__(64) scan_kernel(const float* __restrict__ dtb,
                                                  const float* __restrict__ A_log,
                                                  const float* __restrict__ Dv){
    const int dir = blockIdx.x;
    const int h   = blockIdx.y;
    const int b   = blockIdx.z;
    const int p   = threadIdx.x;
    const float Ah = -expf(A_log[h]);
    const float Dh = Dv[h];
    float st[64];
    #pragma unroll
    for (int n=0;n<64;n++) st[n]=0.f;
    __shared__ float Bs[CT][64];
    __shared__ float Cs[CT][64];
    __shared__ float Xs[CT][64];
    __shared__ float Ts[CT];
    const size_t base = (size_t)b*SEQ;
    for (int t0=0; t0<SEQ; t0+=CT){
        for (int tt=0; tt<CT; tt++){
            int t = dir ? (SEQ-1-(t0+tt)) : (t0+tt);
            size_t r = (base + t)*(size_t)CONVD;
            Bs[tt][p] = g_xbc[r + DIN + p];
            Cs[tt][p] = g_xbc[r + DIN + DS + p];
            Xs[tt][p] = g_xbc[r + h*HD + p];
        }
        if (p < CT){
            int t = dir ? (SEQ-1-(t0+p)) : (t0+p);
            Ts[p] = dtb[(base + t)*NH + h];
        }
        __syncthreads();
        for (int tt=0; tt<CT; tt++){
            float dtv = Ts[tt];
            float dA  = expf(dtv*Ah);
            float dtx = dtv * Xs[tt][p];
            float y0=0.f, y1=0.f, y2v=0.f, y3=0.f;
            #pragma unroll
            for (int n=0;n<64;n+=4){
                st[n+0] = fmaf(dA, st[n+0], dtx*Bs[tt][n+0]);
                st[n+1] = fmaf(dA, st[n+1], dtx*Bs[tt][n+1]);
                st[n+2] = fmaf(dA, st[n+2], dtx*Bs[tt][n+2]);
                st[n+3] = fmaf(dA, st[n+3], dtx*Bs[tt][n+3]);
                y0 = fmaf(st[n+0], Cs[tt][n+0], y0);
                y1 = fmaf(st[n+1], Cs[tt][n+1], y1);
                y2v= fmaf(st[n+2], Cs[tt][n+2], y2v);
                y3 = fmaf(st[n+3], Cs[tt][n+3], y3);
            }
            float yv = (y0+y1) + (y2v+y3);
            int t = dir ? (SEQ-1-(t0+tt)) : (t0+tt);
            if (dir==0) yv = fmaf(Dh, Xs[tt][p], yv);
            atomicAdd(&g_y[(base + t)*(size_t)DIN + h*HD + p], yv);
        }
        __syncthreads();
    }
}

// -------- y2 = rmsnorm(y * silu(z)) * norm_w, rows of 1024, 256 threads ------
__global__ void __launch_bounds__(256) gatednorm_kernel(const float* __restrict__ z,
                                                        const float* __restrict__ w,
                                                        float* __restrict__ out){
    int row = blockIdx.x; int t = threadIdx.x;
    float4 yv = ((const float4*)(g_y + (size_t)row*DIN))[t];
    float4 zv = ((const float4*)(z   + (size_t)row*DIN))[t];
    float4 v;
    v.x = yv.x * siluf(zv.x);
    v.y = yv.y * siluf(zv.y);
    v.z = yv.z * siluf(zv.z);
    v.w = yv.w * siluf(zv.w);
    float ss = v.x*v.x + v.y*v.y + v.z*v.z + v.w*v.w;
    __shared__ float sh[8];
    #pragma unroll
    for (int o=16;o;o>>=1) ss += __shfl_xor_sync(0xffffffffu, ss, o);
    if ((t&31)==0) sh[t>>5] = ss;
    __syncthreads();
    float tot = sh[0]+sh[1]+sh[2]+sh[3]+sh[4]+sh[5]+sh[6]+sh[7];
    float inv = rsqrtf(tot*(1.f/DIN) + EPSR);
    float4 wv = ((const float4*)w)[t];
    float4 o4 = make_float4(v.x*inv*wv.x, v.y*inv*wv.y, v.z*inv*wv.z, v.w*inv*wv.w);
    ((float4*)(out + (size_t)row*DIN))[t] = o4;
}

// -------- h = rmsnorm(2*m), rows of 512, 128 threads --------
__global__ void __launch_bounds__(128) postnorm_kernel(const float* __restrict__ m,
                                                       float* __restrict__ hout){
    int row = blockIdx.x; int t = threadIdx.x;
    float4 mv = ((const float4*)(m + (size_t)row*DM))[t];
    float4 v = make_float4(2.f*mv.x, 2.f*mv.y, 2.f*mv.z, 2.f*mv.w);
    float ss = v.x*v.x + v.y*v.y + v.z*v.z + v.w*v.w;
    __shared__ float sh[4];
    #pragma unroll
    for (int o=16;o;o>>=1) ss += __shfl_xor_sync(0xffffffffu, ss, o);
    if ((t&31)==0) sh[t>>5] = ss;
    __syncthreads();
    float tot = sh[0]+sh[1]+sh[2]+sh[3];
    float inv = rsqrtf(tot*(1.f/DM) + EPSR);
    float4 o4 = make_float4(v.x*inv, v.y*inv, v.z*inv, v.w*inv);
    ((float4*)(hout + (size_t)row*DM))[t] = o4;
}

extern "C" void kernel_launch(void* const* d_in, const int* in_sizes, int n_in,
                              void* d_out, int out_size){
    const float* x      = (const float*)d_in[0];
    const float* mask   = (const float*)d_in[1];
    const float* W_in   = (const float*)d_in[2];
    const float* conv_w = (const float*)d_in[3];
    const float* conv_b = (const float*)d_in[4];
    const float* dt_bias= (const float*)d_in[5];
    const float* A_log  = (const float*)d_in[6];
    const float* Dv     = (const float*)d_in[7];
    const float* norm_w = (const float*)d_in[8];
    const float* W_out  = (const float*)d_in[9];
    const float* W1     = (const float*)d_in[10];
    const float* b1     = (const float*)d_in[11];
    const float* W2     = (const float*)d_in[12];
    const float* b2     = (const float*)d_in[13];

    float* out_x  = (float*)d_out;
    float* out_m  = out_x  + (size_t)NBL*DM;
    float* out_dt = out_m  + (size_t)NBL*DM;
    float* out_z  = out_dt + (size_t)NBL*NH;

    float *pu,*pzx,*pff,*py2;
    cudaGetSymbolAddress((void**)&pu,  g_u);
    cudaGetSymbolAddress((void**)&pzx, g_zx);
    cudaGetSymbolAddress((void**)&pff, g_ff);
    cudaGetSymbolAddress((void**)&py2, g_y2);

    // 1) pre-norm
    prenorm_kernel<<<NBL,128>>>(x, mask, pu);
    // 2) in-projection: (16384 x 512) @ (512 x 2192)
    {
        dim3 g((DPROJ+127)/128, NBL/128);
        sgemm_kernel<0><<<g,256>>>(pu, W_in, pzx, NBL, DPROJ, DM, nullptr, nullptr);
    }
    // 3) conv + silu + mask
    conv_kernel<<<(int)(((long)NBL*CONVD + 255)/256), 256>>>(conv_w, conv_b, mask);
    // 4) dt softplus (writes output dt region; also scan input)
    dt_kernel<<<(NBL*NH + 255)/256, 256>>>(dt_bias, out_dt);
    // 5) z copy to output
    zcopy_kernel<<<(NBL*(DIN/4) + 255)/256, 256>>>(out_z);
    // 6) zero y accumulator
    zero_y_kernel<<<(NBL*DIN/4 + 255)/256, 256>>>();
    // 7) bidirectional scan (fwd adds D*x term; both dirs atomicAdd)
    scan_kernel<<<dim3(2,NH,BATCH), 64>>>(out_dt, A_log, Dv);
    // 8) gated rmsnorm
    gatednorm_kernel<<<NBL,256>>>(out_z, norm_w, py2);
    // 9) out projection -> m
    {
        dim3 g(DM/128, NBL/128);
        sgemm_kernel<0><<<g,256>>>(py2, W_out, out_m, NBL, DM, DIN, nullptr, nullptr);
    }
    // 10) h = rmsnorm(2m) (reuse g_u)
    postnorm_kernel<<<NBL,128>>>(out_m, pu);
    // 11) FFN up: gelu(h@W1 + b1)
    {
        dim3 g(DFF/128, NBL/128);
        sgemm_kernel<1><<<g,256>>>(pu, W1, pff, NBL, DFF, DM, b1, nullptr);
    }
    // 12) FFN down + residual: out_x = 2m + (ff@W2 + b2)
    {
        dim3 g(DM/128, NBL/128);
        sgemm_kernel<2><<<g,256>>>(pff, W2, out_x, NBL, DM, DFF, b2, out_m);
    }
}

// round 3
// speedup vs baseline: 1.8655x; 1.8655x over previous
#include <cuda_runtime.h>
#include <cuda_bf16.h>
#include <math.h>
#include <stdint.h>

#define BATCH 8
#define SEQ   2048
#define NBL   (BATCH*SEQ)          // 16384
#define DM    512
#define DIN   1024
#define NH    16
#define HD    64
#define DS    64
#define CONVD 1152
#define DPROJ 2192
#define DFF   2048
#define EPSR  1e-6f

// ===================== scratch (static device; no cudaMalloc) =====================
static __device__ float g_zx[(size_t)NBL*DPROJ];    // in-proj output (fp32)
static __device__ float g_xbc[(size_t)NBL*CONVD];   // conv+silu output
static __device__ float g_y[(size_t)NBL*DIN];       // scan accumulation
// split-bf16 activations
static __device__ __nv_bfloat16 g_uh[(size_t)NBL*DM],  g_ul[(size_t)NBL*DM];
static __device__ __nv_bfloat16 g_y2h[(size_t)NBL*DIN], g_y2l[(size_t)NBL*DIN];
static __device__ __nv_bfloat16 g_hh[(size_t)NBL*DM],  g_hl[(size_t)NBL*DM];
static __device__ __nv_bfloat16 g_ffh[(size_t)NBL*DFF], g_ffl[(size_t)NBL*DFF];
// split-bf16 transposed weights [N,K]
static __device__ __nv_bfloat16 g_wih[(size_t)DPROJ*DM], g_wil[(size_t)DPROJ*DM];
static __device__ __nv_bfloat16 g_woh[(size_t)DM*DIN],   g_wol[(size_t)DM*DIN];
static __device__ __nv_bfloat16 g_w1h[(size_t)DFF*DM],   g_w1l[(size_t)DFF*DM];
static __device__ __nv_bfloat16 g_w2h[(size_t)DM*DFF],   g_w2l[(size_t)DM*DFF];

// ===================== helpers =====================
__device__ __forceinline__ uint32_t smem_to_u32(const void* smem_ptr) {
    uint32_t addr;
    asm("{ .reg .u64 tmp; cvta.to.shared.u64 tmp, %1; cvt.u32.u64 %0, tmp; }"
        : "=r"(addr) : "l"(smem_ptr));
    return addr;
}
__device__ __forceinline__ void cp_async16(uint32_t dst, const void* src, uint32_t bytes){
    asm volatile("cp.async.cg.shared.global [%0], [%1], 16, %2;"
                 :: "r"(dst), "l"(src), "r"(bytes));
}
#define CP_COMMIT() asm volatile("cp.async.commit_group;")
#define CP_WAIT1()  asm volatile("cp.async.wait_group 1;")
#define CP_WAIT0()  asm volatile("cp.async.wait_group 0;")

__device__ __forceinline__ void ldm_x4(uint32_t addr, uint32_t& r0, uint32_t& r1,
                                       uint32_t& r2, uint32_t& r3){
    asm volatile("ldmatrix.sync.aligned.m8n8.x4.shared.b16 {%0,%1,%2,%3}, [%4];"
                 : "=r"(r0), "=r"(r1), "=r"(r2), "=r"(r3) : "r"(addr));
}
__device__ __forceinline__ void mma16816(float* c, const uint32_t* a, const uint32_t* b){
    asm volatile(
        "mma.sync.aligned.m16n8k16.row.col.f32.bf16.bf16.f32 "
        "{%0,%1,%2,%3}, {%4,%5,%6,%7}, {%8,%9}, {%0,%1,%2,%3};"
        : "+f"(c[0]), "+f"(c[1]), "+f"(c[2]), "+f"(c[3])
        : "r"(a[0]), "r"(a[1]), "r"(a[2]), "r"(a[3]), "r"(b[0]), "r"(b[1]));
}

__device__ __forceinline__ float siluf(float x){ return x / (1.f + expf(-x)); }
__device__ __forceinline__ float geluf(float x){
    float x3 = x*x*x;
    return 0.5f*x*(1.f + tanhf(0.7978845608028654f*(x + 0.044715f*x3)));
}
__device__ __forceinline__ float softplusf(float x){
    return fmaxf(x, 0.f) + log1pf(expf(-fabsf(x)));
}
__device__ __forceinline__ void split_bf16(float v, __nv_bfloat16& h, __nv_bfloat16& l){
    h = __float2bfloat16(v);
    l = __float2bfloat16(v - __bfloat162float(h));
}

// ===================== weight transpose + split: W[K,N] -> T_hi/lo[N,K] ==========
__global__ void wconv_kernel(const float* __restrict__ W,
                             __nv_bfloat16* __restrict__ Th, __nv_bfloat16* __restrict__ Tl,
                             int K, int N){
    __shared__ float tile[32][33];
    int n0 = blockIdx.x*32, k0 = blockIdx.y*32;
    int tx = threadIdx.x, ty = threadIdx.y;   // 32 x 8
    #pragma unroll
    for (int i=0;i<32;i+=8){
        int k = k0+ty+i, n = n0+tx;
        tile[ty+i][tx] = (n < N) ? W[(size_t)k*N + n] : 0.f;
    }
    __syncthreads();
    #pragma unroll
    for (int i=0;i<32;i+=8){
        int n = n0+ty+i, k = k0+tx;
        if (n < N){
            float v = tile[tx][ty+i];
            __nv_bfloat16 h, l; split_bf16(v, h, l);
            Th[(size_t)n*K + k] = h;
            Tl[(size_t)n*K + k] = l;
        }
    }
}

// ===================== split-bf16 HMMA GEMM ======================================
// C[M,N] = A[M,K] @ B[K,N]; A hi/lo [M,K], B hi/lo [N,K] (pre-transposed).
// 128x128 tile, BK=32, cp.async double buffer, 256 threads (warp tile 32x64).
// MODE 0: fp32 store; MODE 1: gelu(acc+bias)->bf16 hi/lo; MODE 2: acc+bias+2*res->fp32
#define BK 32
#define LDSB 80                                  // smem row stride bytes (40 elems)
#define MAT_ELEMS (128*40)                       // per matrix per stage
#define STAGE_ELEMS (4*MAT_ELEMS)                // Ah, Al, Bh, Bl
#define GSMEM_BYTES (2*STAGE_ELEMS*2)            // 81920

template<int MODE>
__global__ void __launch_bounds__(256,1)
mma_gemm(const __nv_bfloat16* __restrict__ Ah, const __nv_bfloat16* __restrict__ Al,
         const __nv_bfloat16* __restrict__ Bh, const __nv_bfloat16* __restrict__ Bl,
         int N, int K,
         float* __restrict__ C, const float* __restrict__ bias,
         const float* __restrict__ res,
         __nv_bfloat16* __restrict__ Oh, __nv_bfloat16* __restrict__ Ol)
{
    extern __shared__ __nv_bfloat16 smem[];
    const uint32_t sb = smem_to_u32(smem);
    const int tid = threadIdx.x;
    const int lane = tid & 31, wid = tid >> 5;
    const int row0 = blockIdx.y * 128;
    const int n0   = blockIdx.x * 128;
    const int wm0 = (wid & 3) * 32;          // warp M offset (4 warps)
    const int wn0 = (wid >> 2) * 64;         // warp N offset (2 warps)

    // per-thread cp.async coords: id in [0,512): r=id>>2, c8=(id&3)*8
    const int r_a  = tid >> 2, c8 = (tid & 3) * 8;
    // per-thread ldmatrix byte offsets
    const uint32_t aoff = (uint32_t)((lane & 15) * LDSB + (lane >> 4) * 16);
    const uint32_t boff = (uint32_t)(((lane & 7) + ((lane & 16) >> 1)) * LDSB + (lane & 8) * 2);

    float acc[2][8][4];
    #pragma unroll
    for (int i=0;i<2;i++)
        #pragma unroll
        for (int j=0;j<8;j++)
            #pragma unroll
            for (int q=0;q<4;q++) acc[i][j][q]=0.f;

    const int nch = K / BK;

    auto issue = [&](int ch){
        const int stg = ch & 1;
        const int k0 = ch * BK;
        uint32_t base = sb + (uint32_t)(stg * STAGE_ELEMS) * 2;
        // A hi/lo: rows r_a and r_a+64
        #pragma unroll
        for (int i=0;i<2;i++){
            int r = r_a + i*64;
            size_t g = (size_t)(row0 + r) * K + k0 + c8;
            uint32_t so = (uint32_t)(r * LDSB + c8 * 2);
            cp_async16(base + so,                      Ah + g, 16);
            cp_async16(base + (uint32_t)MAT_ELEMS*2 + so, Al + g, 16);
        }
        // B hi/lo: rows (n) r_a and r_a+64, zero-fill OOB
        #pragma unroll
        for (int i=0;i<2;i++){
            int r = r_a + i*64;
            int n = n0 + r;
            int valid = (n < N);
            size_t g = (size_t)(valid ? n : 0) * K + k0 + c8;
            uint32_t so = (uint32_t)(r * LDSB + c8 * 2);
            uint32_t bytes = valid ? 16u : 0u;
            cp_async16(base + (uint32_t)(2*MAT_ELEMS)*2 + so, Bh + g, bytes);
            cp_async16(base + (uint32_t)(3*MAT_ELEMS)*2 + so, Bl + g, bytes);
        }
        CP_COMMIT();
    };

    issue(0);
    for (int ch = 0; ch < nch; ch++){
        if (ch + 1 < nch){ issue(ch + 1); CP_WAIT1(); }
        else { CP_WAIT0(); }
        __syncthreads();

        const uint32_t base = sb + (uint32_t)((ch & 1) * STAGE_ELEMS) * 2;
        const uint32_t bAh = base;
        const uint32_t bAl = base + (uint32_t)MAT_ELEMS*2;
        const uint32_t bBh = base + (uint32_t)(2*MAT_ELEMS)*2;
        const uint32_t bBl = base + (uint32_t)(3*MAT_ELEMS)*2;

        #pragma unroll
        for (int ks = 0; ks < BK; ks += 16){
            uint32_t ah[2][4], al[2][4], bh[8][2], bl[8][2];
            #pragma unroll
            for (int mt = 0; mt < 2; mt++){
                uint32_t ao = (uint32_t)((wm0 + mt*16) * LDSB + ks*2) + aoff;
                ldm_x4(bAh + ao, ah[mt][0], ah[mt][1], ah[mt][2], ah[mt][3]);
                ldm_x4(bAl + ao, al[mt][0], al[mt][1], al[mt][2], al[mt][3]);
            }
            #pragma unroll
            for (int p = 0; p < 4; p++){
                uint32_t bo = (uint32_t)((wn0 + p*16) * LDSB + ks*2) + boff;
                ldm_x4(bBh + bo, bh[2*p][0], bh[2*p][1], bh[2*p+1][0], bh[2*p+1][1]);
                ldm_x4(bBl + bo, bl[2*p][0], bl[2*p][1], bl[2*p+1][0], bl[2*p+1][1]);
            }
            #pragma unroll
            for (int mt = 0; mt < 2; mt++)
                #pragma unroll
                for (int nt = 0; nt < 8; nt++){
                    mma16816(acc[mt][nt], ah[mt], bh[nt]);
                    mma16816(acc[mt][nt], ah[mt], bl[nt]);
                    mma16816(acc[mt][nt], al[mt], bh[nt]);
                }
        }
        __syncthreads();
    }

    // ---- epilogue ----
    const int rb = row0 + wm0 + (lane >> 2);
    const int cb = n0 + wn0 + (lane & 3) * 2;
    #pragma unroll
    for (int mt = 0; mt < 2; mt++){
        #pragma unroll
        for (int nt = 0; nt < 8; nt++){
            int c = cb + nt*8;
            if (c >= N) continue;
            #pragma unroll
            for (int half = 0; half < 2; half++){
                int r = rb + mt*16 + half*8;
                float v0 = acc[mt][nt][half*2+0];
                float v1 = acc[mt][nt][half*2+1];
                size_t o = (size_t)r*N + c;
                if (MODE == 0){
                    float2 f2 = make_float2(v0, v1);
                    *(float2*)(C + o) = f2;
                } else if (MODE == 1){
                    v0 = geluf(v0 + bias[c]);
                    v1 = geluf(v1 + bias[c+1]);
                    __nv_bfloat16 h0,l0,h1,l1;
                    split_bf16(v0,h0,l0); split_bf16(v1,h1,l1);
                    __nv_bfloat162 ph2; ph2.x=h0; ph2.y=h1;
                    __nv_bfloat162 pl2; pl2.x=l0; pl2.y=l1;
                    *(__nv_bfloat162*)(Oh + o) = ph2;
                    *(__nv_bfloat162*)(Ol + o) = pl2;
                } else {
                    float2 rv = *(const float2*)(res + o);
                    float2 f2 = make_float2(v0 + bias[c]   + 2.f*rv.x,
                                            v1 + bias[c+1] + 2.f*rv.y);
                    *(float2*)(C + o) = f2;
                }
            }
        }
    }
}

// ===================== u = rmsnorm(x*mask) -> bf16 hi/lo =====================
__global__ void __launch_bounds__(128) prenorm_kernel(const float* __restrict__ x,
                                                      const float* __restrict__ mask,
                                                      __nv_bfloat16* __restrict__ uh,
                                                      __nv_bfloat16* __restrict__ ul){
    int row = blockIdx.x; int t = threadIdx.x;
    float mk = mask[row];
    float4 a = ((const float4*)(x + (size_t)row*DM))[t];
    a.x*=mk; a.y*=mk; a.z*=mk; a.w*=mk;
    float ss = a.x*a.x + a.y*a.y + a.z*a.z + a.w*a.w;
    __shared__ float sh[4];
    #pragma unroll
    for (int o=16;o;o>>=1) ss += __shfl_xor_sync(0xffffffffu, ss, o);
    if ((t&31)==0) sh[t>>5] = ss;
    __syncthreads();
    float inv = rsqrtf((sh[0]+sh[1]+sh[2]+sh[3])*(1.f/DM) + EPSR);
    float v[4] = {a.x*inv, a.y*inv, a.z*inv, a.w*inv};
    __nv_bfloat16 h[4], l[4];
    #pragma unroll
    for (int i=0;i<4;i++) split_bf16(v[i], h[i], l[i]);
    size_t o = (size_t)row*DM + t*4;
    __nv_bfloat162 p;
    p.x=h[0]; p.y=h[1]; *(__nv_bfloat162*)(uh+o)   = p;
    p.x=h[2]; p.y=h[3]; *(__nv_bfloat162*)(uh+o+2) = p;
    p.x=l[0]; p.y=l[1]; *(__nv_bfloat162*)(ul+o)   = p;
    p.x=l[2]; p.y=l[3]; *(__nv_bfloat162*)(ul+o+2) = p;
}

// ===================== conv + silu + mask =====================
__global__ void conv_kernel(const float* __restrict__ cw, const float* __restrict__ cb,
                            const float* __restrict__ mask){
    long idx = (long)blockIdx.x*blockDim.x + threadIdx.x;
    if (idx >= (long)NBL*CONVD) return;
    int c = (int)(idx % CONVD);
    long bl = idx / CONVD;
    int l = (int)(bl % SEQ);
    float acc = cb[c];
    #pragma unroll
    for (int i=0;i<4;i++){
        int ls = l + i - 3;
        if (ls >= 0)
            acc += g_zx[(size_t)(bl + (i-3))*DPROJ + DIN + c] * cw[c*4 + i];
    }
    g_xbc[idx] = siluf(acc) * mask[bl];
}

// ===================== dt = softplus(dt_raw + dt_bias) =====================
__global__ void dt_kernel(const float* __restrict__ dt_bias, float* __restrict__ out_dt){
    int idx = blockIdx.x*blockDim.x + threadIdx.x;
    if (idx >= NBL*NH) return;
    int hh = idx & (NH-1);
    long bl = idx >> 4;
    float v = g_zx[(size_t)bl*DPROJ + (DIN+CONVD) + hh] + dt_bias[hh];
    out_dt[idx] = softplusf(v);
}

// ===================== z copy to output =====================
__global__ void zcopy_kernel(float* __restrict__ out_z){
    int idx = blockIdx.x*blockDim.x + threadIdx.x;
    if (idx >= NBL*(DIN/4)) return;
    long bl = idx >> 8; int c4 = idx & 255;
    ((float4*)out_z)[idx] = *(const float4*)&g_zx[(size_t)bl*DPROJ + c4*4];
}

__global__ void zero_y_kernel(){
    long i = (long)blockIdx.x*blockDim.x + threadIdx.x;
    if (i < (long)NBL*DIN/4) ((float4*)g_y)[i] = make_float4(0.f,0.f,0.f,0.f);
}

// ===================== bidirectional SSM scan =====================
#define CT 32
__global__ void __launch_bounds__(64) scan_kernel(const float* __restrict__ dtb,
                                                  const float* __restrict__ A_log,
                                                  const float* __restrict__ Dv){
    const int dir = blockIdx.x;
    const int h   = blockIdx.y;
    const int b   = blockIdx.z;
    const int p   = threadIdx.x;
    const float Ah = -expf(A_log[h]);
    const float Dh = Dv[h];
    float st[64];
    #pragma unroll
    for (int n=0;n<64;n++) st[n]=0.f;
    __shared__ float Bs[CT][64];
    __shared__ float Cs[CT][64];
    __shared__ float Xs[CT][64];
    __shared__ float Ts[CT];
    const size_t base = (size_t)b*SEQ;
    for (int t0=0; t0<SEQ; t0+=CT){
        for (int tt=0; tt<CT; tt++){
            int t = dir ? (SEQ-1-(t0+tt)) : (t0+tt);
            size_t r = (base + t)*(size_t)CONVD;
            Bs[tt][p] = g_xbc[r + DIN + p];
            Cs[tt][p] = g_xbc[r + DIN + DS + p];
            Xs[tt][p] = g_xbc[r + h*HD + p];
        }
        if (p < CT){
            int t = dir ? (SEQ-1-(t0+p)) : (t0+p);
            Ts[p] = dtb[(base + t)*NH + h];
        }
        __syncthreads();
        for (int tt=0; tt<CT; tt++){
            float dtv = Ts[tt];
            float dA  = expf(dtv*Ah);
            float dtx = dtv * Xs[tt][p];
            float y0=0.f, y1=0.f, y2v=0.f, y3=0.f;
            #pragma unroll
            for (int n=0;n<64;n+=4){
                st[n+0] = fmaf(dA, st[n+0], dtx*Bs[tt][n+0]);
                st[n+1] = fmaf(dA, st[n+1], dtx*Bs[tt][n+1]);
                st[n+2] = fmaf(dA, st[n+2], dtx*Bs[tt][n+2]);
                st[n+3] = fmaf(dA, st[n+3], dtx*Bs[tt][n+3]);
                y0 = fmaf(st[n+0], Cs[tt][n+0], y0);
                y1 = fmaf(st[n+1], Cs[tt][n+1], y1);
                y2v= fmaf(st[n+2], Cs[tt][n+2], y2v);
                y3 = fmaf(st[n+3], Cs[tt][n+3], y3);
            }
            float yv = (y0+y1) + (y2v+y3);
            int t = dir ? (SEQ-1-(t0+tt)) : (t0+tt);
            if (dir==0) yv = fmaf(Dh, Xs[tt][p], yv);
            atomicAdd(&g_y[(base + t)*(size_t)DIN + h*HD + p], yv);
        }
        __syncthreads();
    }
}

// ===================== y2 = rmsnorm(y * silu(z)) * norm_w -> bf16 hi/lo ======
__global__ void __launch_bounds__(256) gatednorm_kernel(const float* __restrict__ z,
                                                        const float* __restrict__ w,
                                                        __nv_bfloat16* __restrict__ yh,
                                                        __nv_bfloat16* __restrict__ yl){
    int row = blockIdx.x; int t = threadIdx.x;
    float4 yv = ((const float4*)(g_y + (size_t)row*DIN))[t];
    float4 zv = ((const float4*)(z   + (size_t)row*DIN))[t];
    float4 v;
    v.x = yv.x * siluf(zv.x);
    v.y = yv.y * siluf(zv.y);
    v.z = yv.z * siluf(zv.z);
    v.w = yv.w * siluf(zv.w);
    float ss = v.x*v.x + v.y*v.y + v.z*v.z + v.w*v.w;
    __shared__ float sh[8];
    #pragma unroll
    for (int o=16;o;o>>=1) ss += __shfl_xor_sync(0xffffffffu, ss, o);
    if ((t&31)==0) sh[t>>5] = ss;
    __syncthreads();
    float tot = sh[0]+sh[1]+sh[2]+sh[3]+sh[4]+sh[5]+sh[6]+sh[7];
    float inv = rsqrtf(tot*(1.f/DIN) + EPSR);
    float4 wv = ((const float4*)w)[t];
    float o4[4] = {v.x*inv*wv.x, v.y*inv*wv.y, v.z*inv*wv.z, v.w*inv*wv.w};
    __nv_bfloat16 h[4], l[4];
    #pragma unroll
    for (int i=0;i<4;i++) split_bf16(o4[i], h[i], l[i]);
    size_t o = (size_t)row*DIN + t*4;
    __nv_bfloat162 p;
    p.x=h[0]; p.y=h[1]; *(__nv_bfloat162*)(yh+o)   = p;
    p.x=h[2]; p.y=h[3]; *(__nv_bfloat162*)(yh+o+2) = p;
    p.x=l[0]; p.y=l[1]; *(__nv_bfloat162*)(yl+o)   = p;
    p.x=l[2]; p.y=l[3]; *(__nv_bfloat162*)(yl+o+2) = p;
}

// ===================== h = rmsnorm(2*m) -> bf16 hi/lo =====================
__global__ void __launch_bounds__(128) postnorm_kernel(const float* __restrict__ m,
                                                       __nv_bfloat16* __restrict__ hh,
                                                       __nv_bfloat16* __restrict__ hl){
    int row = blockIdx.x; int t = threadIdx.x;
    float4 mv = ((const float4*)(m + (size_t)row*DM))[t];
    float4 v = make_float4(2.f*mv.x, 2.f*mv.y, 2.f*mv.z, 2.f*mv.w);
    float ss = v.x*v.x + v.y*v.y + v.z*v.z + v.w*v.w;
    __shared__ float sh[4];
    #pragma unroll
    for (int o=16;o;o>>=1) ss += __shfl_xor_sync(0xffffffffu, ss, o);
    if ((t&31)==0) sh[t>>5] = ss;
    __syncthreads();
    float inv = rsqrtf((sh[0]+sh[1]+sh[2]+sh[3])*(1.f/DM) + EPSR);
    float o4[4] = {v.x*inv, v.y*inv, v.z*inv, v.w*inv};
    __nv_bfloat16 h[4], l[4];
    #pragma unroll
    for (int i=0;i<4;i++) split_bf16(o4[i], h[i], l[i]);
    size_t o = (size_t)row*DM + t*4;
    __nv_bfloat162 p;
    p.x=h[0]; p.y=h[1]; *(__nv_bfloat162*)(hh+o)   = p;
    p.x=h[2]; p.y=h[3]; *(__nv_bfloat162*)(hh+o+2) = p;
    p.x=l[0]; p.y=l[1]; *(__nv_bfloat162*)(hl+o)   = p;
    p.x=l[2]; p.y=l[3]; *(__nv_bfloat162*)(hl+o+2) = p;
}

extern "C" void kernel_launch(void* const* d_in, const int* in_sizes, int n_in,
                              void* d_out, int out_size){
    const float* x      = (const float*)d_in[0];
    const float* mask   = (const float*)d_in[1];
    const float* W_in   = (const float*)d_in[2];
    const float* conv_w = (const float*)d_in[3];
    const float* conv_b = (const float*)d_in[4];
    const float* dt_bias= (const float*)d_in[5];
    const float* A_log  = (const float*)d_in[6];
    const float* Dv     = (const float*)d_in[7];
    const float* norm_w = (const float*)d_in[8];
    const float* W_out  = (const float*)d_in[9];
    const float* W1     = (const float*)d_in[10];
    const float* b1     = (const float*)d_in[11];
    const float* W2     = (const float*)d_in[12];
    const float* b2     = (const float*)d_in[13];

    float* out_x  = (float*)d_out;
    float* out_m  = out_x  + (size_t)NBL*DM;
    float* out_dt = out_m  + (size_t)NBL*DM;
    float* out_z  = out_dt + (size_t)NBL*NH;

    float *pzx;
    __nv_bfloat16 *puh,*pul,*py2h,*py2l,*phh,*phl,*pffh,*pffl;
    __nv_bfloat16 *pwih,*pwil,*pwoh,*pwol,*pw1h,*pw1l,*pw2h,*pw2l;
    cudaGetSymbolAddress((void**)&pzx,  g_zx);
    cudaGetSymbolAddress((void**)&puh,  g_uh);  cudaGetSymbolAddress((void**)&pul,  g_ul);
    cudaGetSymbolAddress((void**)&py2h, g_y2h); cudaGetSymbolAddress((void**)&py2l, g_y2l);
    cudaGetSymbolAddress((void**)&phh,  g_hh);  cudaGetSymbolAddress((void**)&phl,  g_hl);
    cudaGetSymbolAddress((void**)&pffh, g_ffh); cudaGetSymbolAddress((void**)&pffl, g_ffl);
    cudaGetSymbolAddress((void**)&pwih, g_wih); cudaGetSymbolAddress((void**)&pwil, g_wil);
    cudaGetSymbolAddress((void**)&pwoh, g_woh); cudaGetSymbolAddress((void**)&pwol, g_wol);
    cudaGetSymbolAddress((void**)&pw1h, g_w1h); cudaGetSymbolAddress((void**)&pw1l, g_w1l);
    cudaGetSymbolAddress((void**)&pw2h, g_w2h); cudaGetSymbolAddress((void**)&pw2l, g_w2l);

    cudaFuncSetAttribute(mma_gemm<0>, cudaFuncAttributeMaxDynamicSharedMemorySize, GSMEM_BYTES);
    cudaFuncSetAttribute(mma_gemm<1>, cudaFuncAttributeMaxDynamicSharedMemorySize, GSMEM_BYTES);
    cudaFuncSetAttribute(mma_gemm<2>, cudaFuncAttributeMaxDynamicSharedMemorySize, GSMEM_BYTES);

    dim3 wb(32,8);
    wconv_kernel<<<dim3((DPROJ+31)/32, DM/32),   wb>>>(W_in,  pwih, pwil, DM,  DPROJ);
    wconv_kernel<<<dim3((DM+31)/32,    DIN/32),  wb>>>(W_out, pwoh, pwol, DIN, DM);
    wconv_kernel<<<dim3((DFF+31)/32,   DM/32),   wb>>>(W1,    pw1h, pw1l, DM,  DFF);
    wconv_kernel<<<dim3((DM+31)/32,    DFF/32),  wb>>>(W2,    pw2h, pw2l, DFF, DM);

    // 1) pre-norm -> bf16 split
    prenorm_kernel<<<NBL,128>>>(x, mask, puh, pul);
    // 2) in-projection
    mma_gemm<0><<<dim3((DPROJ+127)/128, NBL/128), 256, GSMEM_BYTES>>>(
        puh, pul, pwih, pwil, DPROJ, DM, pzx, nullptr, nullptr, nullptr, nullptr);
    // 3) conv + silu + mask
    conv_kernel<<<(int)(((long)NBL*CONVD + 255)/256), 256>>>(conv_w, conv_b, mask);
    // 4) dt softplus
    dt_kernel<<<(NBL*NH + 255)/256, 256>>>(dt_bias, out_dt);
    // 5) z copy
    zcopy_kernel<<<(NBL*(DIN/4) + 255)/256, 256>>>(out_z);
    // 6) zero y
    zero_y_kernel<<<(NBL*DIN/4 + 255)/256, 256>>>();
    // 7) bidirectional scan
    scan_kernel<<<dim3(2,NH,BATCH), 64>>>(out_dt, A_log, Dv);
    // 8) gated rmsnorm -> bf16 split
    gatednorm_kernel<<<NBL,256>>>(out_z, norm_w, py2h, py2l);
    // 9) out projection -> m
    mma_gemm<0><<<dim3(DM/128, NBL/128), 256, GSMEM_BYTES>>>(
        py2h, py2l, pwoh, pwol, DM, DIN, out_m, nullptr, nullptr, nullptr, nullptr);
    // 10) h = rmsnorm(2m)
    postnorm_kernel<<<NBL,128>>>(out_m, phh, phl);
    // 11) FFN up
    mma_gemm<1><<<dim3(DFF/128, NBL/128), 256, GSMEM_BYTES>>>(
        phh, phl, pw1h, pw1l, DFF, DM, nullptr, b1, nullptr, pffh, pffl);
    // 12) FFN down + residual
    mma_gemm<2><<<dim3(DM/128, NBL/128), 256, GSMEM_BYTES>>>(
        pffh, pffl, pw2h, pw2l, DM, DFF, out_x, b2, out_m, nullptr, nullptr);
}

// round 4
// speedup vs baseline: 1.9436x; 1.0419x over previous
#include <cuda_runtime.h>
#include <cuda_bf16.h>
#include <math.h>
#include <stdint.h>

#define BATCH 8
#define SEQ   2048
#define NBL   (BATCH*SEQ)          // 16384
#define DM    512
#define DIN   1024
#define NH    16
#define HD    64
#define DS    64
#define CONVD 1152
#define DPROJ 2192
#define DFF   2048
#define EPSR  1e-6f

// ===================== scratch (static device; no cudaMalloc) =====================
static __device__ float g_xraw[(size_t)NBL*CONVD];  // in-proj xBC (pre-conv), compact
static __device__ float g_xbc[(size_t)NBL*CONVD];   // conv+silu output
static __device__ float g_y[(size_t)NBL*DIN];       // scan accumulation
// split-bf16 activations
static __device__ __nv_bfloat16 g_uh[(size_t)NBL*DM],  g_ul[(size_t)NBL*DM];
static __device__ __nv_bfloat16 g_y2h[(size_t)NBL*DIN], g_y2l[(size_t)NBL*DIN];
static __device__ __nv_bfloat16 g_hh[(size_t)NBL*DM],  g_hl[(size_t)NBL*DM];
static __device__ __nv_bfloat16 g_ffh[(size_t)NBL*DFF], g_ffl[(size_t)NBL*DFF];
// split-bf16 transposed weights [N,K]
static __device__ __nv_bfloat16 g_wih[(size_t)DPROJ*DM], g_wil[(size_t)DPROJ*DM];
static __device__ __nv_bfloat16 g_woh[(size_t)DM*DIN],   g_wol[(size_t)DM*DIN];
static __device__ __nv_bfloat16 g_w1h[(size_t)DFF*DM],   g_w1l[(size_t)DFF*DM];
static __device__ __nv_bfloat16 g_w2h[(size_t)DM*DFF],   g_w2l[(size_t)DM*DFF];

// ===================== helpers =====================
__device__ __forceinline__ uint32_t smem_to_u32(const void* smem_ptr) {
    uint32_t addr;
    asm("{ .reg .u64 tmp; cvta.to.shared.u64 tmp, %1; cvt.u32.u64 %0, tmp; }"
        : "=r"(addr) : "l"(smem_ptr));
    return addr;
}
__device__ __forceinline__ void cp_async16(uint32_t dst, const void* src, uint32_t bytes){
    asm volatile("cp.async.cg.shared.global [%0], [%1], 16, %2;"
                 :: "r"(dst), "l"(src), "r"(bytes));
}
#define CP_COMMIT() asm volatile("cp.async.commit_group;")
#define CP_WAIT1()  asm volatile("cp.async.wait_group 1;")
#define CP_WAIT0()  asm volatile("cp.async.wait_group 0;")

__device__ __forceinline__ void ldm_x4(uint32_t addr, uint32_t& r0, uint32_t& r1,
                                       uint32_t& r2, uint32_t& r3){
    asm volatile("ldmatrix.sync.aligned.m8n8.x4.shared.b16 {%0,%1,%2,%3}, [%4];"
                 : "=r"(r0), "=r"(r1), "=r"(r2), "=r"(r3) : "r"(addr));
}
__device__ __forceinline__ void mma16816(float* c, const uint32_t* a, const uint32_t* b){
    asm volatile(
        "mma.sync.aligned.m16n8k16.row.col.f32.bf16.bf16.f32 "
        "{%0,%1,%2,%3}, {%4,%5,%6,%7}, {%8,%9}, {%0,%1,%2,%3};"
        : "+f"(c[0]), "+f"(c[1]), "+f"(c[2]), "+f"(c[3])
        : "r"(a[0]), "r"(a[1]), "r"(a[2]), "r"(a[3]), "r"(b[0]), "r"(b[1]));
}

__device__ __forceinline__ float siluf(float x){ return x / (1.f + expf(-x)); }
__device__ __forceinline__ float geluf(float x){
    float x3 = x*x*x;
    return 0.5f*x*(1.f + tanhf(0.7978845608028654f*(x + 0.044715f*x3)));
}
__device__ __forceinline__ float softplusf(float x){
    return fmaxf(x, 0.f) + log1pf(expf(-fabsf(x)));
}
__device__ __forceinline__ void split_bf16(float v, __nv_bfloat16& h, __nv_bfloat16& l){
    h = __float2bfloat16(v);
    l = __float2bfloat16(v - __bfloat162float(h));
}

// ===================== weight transpose + split: W[K,N] -> T_hi/lo[N,K] ==========
__global__ void wconv_kernel(const float* __restrict__ W,
                             __nv_bfloat16* __restrict__ Th, __nv_bfloat16* __restrict__ Tl,
                             int K, int N){
    __shared__ float tile[32][33];
    int n0 = blockIdx.x*32, k0 = blockIdx.y*32;
    int tx = threadIdx.x, ty = threadIdx.y;   // 32 x 8
    #pragma unroll
    for (int i=0;i<32;i+=8){
        int k = k0+ty+i, n = n0+tx;
        tile[ty+i][tx] = (n < N) ? W[(size_t)k*N + n] : 0.f;
    }
    __syncthreads();
    #pragma unroll
    for (int i=0;i<32;i+=8){
        int n = n0+ty+i, k = k0+tx;
        if (n < N){
            float v = tile[tx][ty+i];
            __nv_bfloat16 h, l; split_bf16(v, h, l);
            Th[(size_t)n*K + k] = h;
            Tl[(size_t)n*K + k] = l;
        }
    }
}

// ===================== split-bf16 HMMA GEMM ======================================
// C[M,N] = A[M,K] @ B[K,N]; A hi/lo [M,K], B hi/lo [N,K] (pre-transposed).
// 128x128 tile, BK=32, 3-stage cp.async pipeline, 256 threads (warp tile 32x64).
// MODE 0: fp32 store; MODE 1: gelu(acc+bias)->bf16 hi/lo; MODE 2: acc+bias+2*res->fp32
// MODE 3: in-proj fused split (z -> z_out fp32, xBC -> xraw fp32, dt -> softplus -> dt_out)
#define BK 32
#define LDSB 80                                  // smem row stride bytes (40 elems)
#define MAT_ELEMS (128*40)                       // per matrix per stage
#define STAGE_ELEMS (4*MAT_ELEMS)                // Ah, Al, Bh, Bl
#define STAGE_BYTES (STAGE_ELEMS*2)              // 40960
#define GSMEM_BYTES (3*STAGE_BYTES)              // 122880

template<int MODE>
__global__ void __launch_bounds__(256,1)
mma_gemm(const __nv_bfloat16* __restrict__ Ah, const __nv_bfloat16* __restrict__ Al,
         const __nv_bfloat16* __restrict__ Bh, const __nv_bfloat16* __restrict__ Bl,
         int N, int K,
         float* __restrict__ C, const float* __restrict__ bias,
         const float* __restrict__ res,
         __nv_bfloat16* __restrict__ Oh, __nv_bfloat16* __restrict__ Ol,
         float* __restrict__ z_out, float* __restrict__ xraw,
         float* __restrict__ dt_out, const float* __restrict__ dtb)
{
    extern __shared__ __nv_bfloat16 smem[];
    const uint32_t sb = smem_to_u32(smem);
    const int tid = threadIdx.x;
    const int lane = tid & 31, wid = tid >> 5;
    const int row0 = blockIdx.y * 128;
    const int n0   = blockIdx.x * 128;
    const int wm0 = (wid & 3) * 32;          // warp M offset (4 warps)
    const int wn0 = (wid >> 2) * 64;         // warp N offset (2 warps)

    const int r_a  = tid >> 2, c8 = (tid & 3) * 8;
    const uint32_t aoff = (uint32_t)((lane & 15) * LDSB + (lane >> 4) * 16);
    const uint32_t boff = (uint32_t)(((lane & 7) + ((lane & 16) >> 1)) * LDSB + (lane & 8) * 2);

    float acc[2][8][4];
    #pragma unroll
    for (int i=0;i<2;i++)
        #pragma unroll
        for (int j=0;j<8;j++)
            #pragma unroll
            for (int q=0;q<4;q++) acc[i][j][q]=0.f;

    const int nch = K / BK;

    auto issue = [&](int ch){
        const int k0 = ch * BK;
        uint32_t base = sb + (uint32_t)((ch % 3) * STAGE_BYTES);
        #pragma unroll
        for (int i=0;i<2;i++){
            int r = r_a + i*64;
            size_t g = (size_t)(row0 + r) * K + k0 + c8;
            uint32_t so = (uint32_t)(r * LDSB + c8 * 2);
            cp_async16(base + so,                         Ah + g, 16);
            cp_async16(base + (uint32_t)MAT_ELEMS*2 + so, Al + g, 16);
        }
        #pragma unroll
        for (int i=0;i<2;i++){
            int r = r_a + i*64;
            int n = n0 + r;
            int valid = (n < N);
            size_t g = (size_t)(valid ? n : 0) * K + k0 + c8;
            uint32_t so = (uint32_t)(r * LDSB + c8 * 2);
            uint32_t bytes = valid ? 16u : 0u;
            cp_async16(base + (uint32_t)(2*MAT_ELEMS)*2 + so, Bh + g, bytes);
            cp_async16(base + (uint32_t)(3*MAT_ELEMS)*2 + so, Bl + g, bytes);
        }
        CP_COMMIT();
    };

    issue(0); issue(1);
    for (int ch = 0; ch < nch; ch++){
        if (ch + 1 < nch) CP_WAIT1(); else CP_WAIT0();
        __syncthreads();
        if (ch + 2 < nch) issue(ch + 2);

        const uint32_t base = sb + (uint32_t)((ch % 3) * STAGE_BYTES);
        const uint32_t bAh = base;
        const uint32_t bAl = base + (uint32_t)MAT_ELEMS*2;
        const uint32_t bBh = base + (uint32_t)(2*MAT_ELEMS)*2;
        const uint32_t bBl = base + (uint32_t)(3*MAT_ELEMS)*2;

        #pragma unroll
        for (int ks = 0; ks < BK; ks += 16){
            uint32_t ah[2][4], al[2][4], bh[8][2], bl[8][2];
            #pragma unroll
            for (int mt = 0; mt < 2; mt++){
                uint32_t ao = (uint32_t)((wm0 + mt*16) * LDSB + ks*2) + aoff;
                ldm_x4(bAh + ao, ah[mt][0], ah[mt][1], ah[mt][2], ah[mt][3]);
                ldm_x4(bAl + ao, al[mt][0], al[mt][1], al[mt][2], al[mt][3]);
            }
            #pragma unroll
            for (int p = 0; p < 4; p++){
                uint32_t bo = (uint32_t)((wn0 + p*16) * LDSB + ks*2) + boff;
                ldm_x4(bBh + bo, bh[2*p][0], bh[2*p][1], bh[2*p+1][0], bh[2*p+1][1]);
                ldm_x4(bBl + bo, bl[2*p][0], bl[2*p][1], bl[2*p+1][0], bl[2*p+1][1]);
            }
            // pass-grouped: 16 independent MMAs per pass (acc reuse distance = 16)
            #pragma unroll
            for (int mt = 0; mt < 2; mt++)
                #pragma unroll
                for (int nt = 0; nt < 8; nt++)
                    mma16816(acc[mt][nt], ah[mt], bh[nt]);
            #pragma unroll
            for (int mt = 0; mt < 2; mt++)
                #pragma unroll
                for (int nt = 0; nt < 8; nt++)
                    mma16816(acc[mt][nt], ah[mt], bl[nt]);
            #pragma unroll
            for (int mt = 0; mt < 2; mt++)
                #pragma unroll
                for (int nt = 0; nt < 8; nt++)
                    mma16816(acc[mt][nt], al[mt], bh[nt]);
        }
        __syncthreads();
    }

    // ---- epilogue ----
    const int rb = row0 + wm0 + (lane >> 2);
    const int cb = n0 + wn0 + (lane & 3) * 2;
    #pragma unroll
    for (int mt = 0; mt < 2; mt++){
        #pragma unroll
        for (int nt = 0; nt < 8; nt++){
            int c = cb + nt*8;
            if (c >= N) continue;
            #pragma unroll
            for (int half = 0; half < 2; half++){
                int r = rb + mt*16 + half*8;
                float v0 = acc[mt][nt][half*2+0];
                float v1 = acc[mt][nt][half*2+1];
                size_t o = (size_t)r*N + c;
                if (MODE == 0){
                    *(float2*)(C + o) = make_float2(v0, v1);
                } else if (MODE == 1){
                    v0 = geluf(v0 + bias[c]);
                    v1 = geluf(v1 + bias[c+1]);
                    __nv_bfloat16 h0,l0,h1,l1;
                    split_bf16(v0,h0,l0); split_bf16(v1,h1,l1);
                    __nv_bfloat162 ph2; ph2.x=h0; ph2.y=h1;
                    __nv_bfloat162 pl2; pl2.x=l0; pl2.y=l1;
                    *(__nv_bfloat162*)(Oh + o) = ph2;
                    *(__nv_bfloat162*)(Ol + o) = pl2;
                } else if (MODE == 2){
                    float2 rv = *(const float2*)(res + o);
                    *(float2*)(C + o) = make_float2(v0 + bias[c]   + 2.f*rv.x,
                                                    v1 + bias[c+1] + 2.f*rv.y);
                } else {
                    // MODE 3: in-projection routing
                    if (c < DIN){
                        *(float2*)(z_out + (size_t)r*DIN + c) = make_float2(v0, v1);
                    } else if (c < DIN + CONVD){
                        *(float2*)(xraw + (size_t)r*CONVD + (c - DIN)) = make_float2(v0, v1);
                    } else {
                        int hh2 = c - (DIN + CONVD);
                        dt_out[(size_t)r*NH + hh2]     = softplusf(v0 + dtb[hh2]);
                        dt_out[(size_t)r*NH + hh2 + 1] = softplusf(v1 + dtb[hh2+1]);
                    }
                }
            }
        }
    }
}

// ===================== u = rmsnorm(x*mask) -> bf16 hi/lo =====================
__global__ void __launch_bounds__(128) prenorm_kernel(const float* __restrict__ x,
                                                      const float* __restrict__ mask,
                                                      __nv_bfloat16* __restrict__ uh,
                                                      __nv_bfloat16* __restrict__ ul){
    int row = blockIdx.x; int t = threadIdx.x;
    float mk = mask[row];
    float4 a = ((const float4*)(x + (size_t)row*DM))[t];
    a.x*=mk; a.y*=mk; a.z*=mk; a.w*=mk;
    float ss = a.x*a.x + a.y*a.y + a.z*a.z + a.w*a.w;
    __shared__ float sh[4];
    #pragma unroll
    for (int o=16;o;o>>=1) ss += __shfl_xor_sync(0xffffffffu, ss, o);
    if ((t&31)==0) sh[t>>5] = ss;
    __syncthreads();
    float inv = rsqrtf((sh[0]+sh[1]+sh[2]+sh[3])*(1.f/DM) + EPSR);
    float v[4] = {a.x*inv, a.y*inv, a.z*inv, a.w*inv};
    __nv_bfloat16 h[4], l[4];
    #pragma unroll
    for (int i=0;i<4;i++) split_bf16(v[i], h[i], l[i]);
    size_t o = (size_t)row*DM + t*4;
    __nv_bfloat162 p;
    p.x=h[0]; p.y=h[1]; *(__nv_bfloat162*)(uh+o)   = p;
    p.x=h[2]; p.y=h[3]; *(__nv_bfloat162*)(uh+o+2) = p;
    p.x=l[0]; p.y=l[1]; *(__nv_bfloat162*)(ul+o)   = p;
    p.x=l[2]; p.y=l[3]; *(__nv_bfloat162*)(ul+o+2) = p;
}

// ===================== conv + silu + mask =====================
__global__ void conv_kernel(const float* __restrict__ cw, const float* __restrict__ cb,
                            const float* __restrict__ mask){
    long idx = (long)blockIdx.x*blockDim.x + threadIdx.x;
    if (idx >= (long)NBL*CONVD) return;
    int c = (int)(idx % CONVD);
    long bl = idx / CONVD;
    int l = (int)(bl % SEQ);
    float acc = cb[c];
    #pragma unroll
    for (int i=0;i<4;i++){
        int ls = l + i - 3;
        if (ls >= 0)
            acc += g_xraw[(size_t)(bl + (i-3))*CONVD + c] * cw[c*4 + i];
    }
    g_xbc[idx] = siluf(acc) * mask[bl];
}

__global__ void zero_y_kernel(){
    long i = (long)blockIdx.x*blockDim.x + threadIdx.x;
    if (i < (long)NBL*DIN/4) ((float4*)g_y)[i] = make_float4(0.f,0.f,0.f,0.f);
}

// ===================== bidirectional SSM scan (n-split, 128 threads) =============
// grid (2, NH, BATCH). Thread pair (2p, 2p+1) owns state row p; each handles 32
// of 64 state cols (odd half rotated by 16 for bank-conflict-free smem reads).
#define CT 32
__global__ void __launch_bounds__(128) scan_kernel(const float* __restrict__ dtb,
                                                   const float* __restrict__ A_log,
                                                   const float* __restrict__ Dv){
    const int dir = blockIdx.x;
    const int h   = blockIdx.y;
    const int b   = blockIdx.z;
    const int tid = threadIdx.x;
    const int p    = tid >> 1;
    const int half = tid & 1;
    const int nbase = half << 5;   // 0 or 32
    const int rot   = half << 4;   // 0 or 16
    const float Ah = -expf(A_log[h]);
    const float Dh = Dv[h];
    float st[32];
    #pragma unroll
    for (int j=0;j<32;j++) st[j]=0.f;
    __shared__ float Bs[CT][64];
    __shared__ float Cs[CT][64];
    __shared__ float Xs[CT][64];
    __shared__ float Ts[CT];
    const size_t base = (size_t)b*SEQ;
    for (int t0=0; t0<SEQ; t0+=CT){
        for (int idx = tid; idx < CT*64; idx += 128){
            int tt = idx >> 6, pp = idx & 63;
            int t = dir ? (SEQ-1-(t0+tt)) : (t0+tt);
            size_t r = (base + t)*(size_t)CONVD;
            Bs[tt][pp] = g_xbc[r + DIN + pp];
            Cs[tt][pp] = g_xbc[r + DIN + DS + pp];
            Xs[tt][pp] = g_xbc[r + h*HD + pp];
        }
        if (tid < CT){
            int t = dir ? (SEQ-1-(t0+tid)) : (t0+tid);
            Ts[tid] = dtb[(base + t)*NH + h];
        }
        __syncthreads();
        for (int tt=0; tt<CT; tt++){
            float dtv = Ts[tt];
            float dA  = expf(dtv*Ah);
            float xv  = Xs[tt][p];
            float dtx = dtv * xv;
            float y = 0.f;
            #pragma unroll
            for (int j=0;j<32;j++){
                int n = nbase + ((j + rot) & 31);
                st[j] = fmaf(dA, st[j], dtx*Bs[tt][n]);
                y = fmaf(st[j], Cs[tt][n], y);
            }
            y += __shfl_xor_sync(0xffffffffu, y, 1);
            if (half == 0){
                int t = dir ? (SEQ-1-(t0+tt)) : (t0+tt);
                float yv = y;
                if (dir==0) yv = fmaf(Dh, xv, yv);
                atomicAdd(&g_y[(base + t)*(size_t)DIN + h*HD + p], yv);
            }
        }
        __syncthreads();
    }
}

// ===================== y2 = rmsnorm(y * silu(z)) * norm_w -> bf16 hi/lo ======
__global__ void __launch_bounds__(256) gatednorm_kernel(const float* __restrict__ z,
                                                        const float* __restrict__ w,
                                                        __nv_bfloat16* __restrict__ yh,
                                                        __nv_bfloat16* __restrict__ yl){
    int row = blockIdx.x; int t = threadIdx.x;
    float4 yv = ((const float4*)(g_y + (size_t)row*DIN))[t];
    float4 zv = ((const float4*)(z   + (size_t)row*DIN))[t];
    float4 v;
    v.x = yv.x * siluf(zv.x);
    v.y = yv.y * siluf(zv.y);
    v.z = yv.z * siluf(zv.z);
    v.w = yv.w * siluf(zv.w);
    float ss = v.x*v.x + v.y*v.y + v.z*v.z + v.w*v.w;
    __shared__ float sh[8];
    #pragma unroll
    for (int o=16;o;o>>=1) ss += __shfl_xor_sync(0xffffffffu, ss, o);
    if ((t&31)==0) sh[t>>5] = ss;
    __syncthreads();
    float tot = sh[0]+sh[1]+sh[2]+sh[3]+sh[4]+sh[5]+sh[6]+sh[7];
    float inv = rsqrtf(tot*(1.f/DIN) + EPSR);
    float4 wv = ((const float4*)w)[t];
    float o4[4] = {v.x*inv*wv.x, v.y*inv*wv.y, v.z*inv*wv.z, v.w*inv*wv.w};
    __nv_bfloat16 h[4], l[4];
    #pragma unroll
    for (int i=0;i<4;i++) split_bf16(o4[i], h[i], l[i]);
    size_t o = (size_t)row*DIN + t*4;
    __nv_bfloat162 p;
    p.x=h[0]; p.y=h[1]; *(__nv_bfloat162*)(yh+o)   = p;
    p.x=h[2]; p.y=h[3]; *(__nv_bfloat162*)(yh+o+2) = p;
    p.x=l[0]; p.y=l[1]; *(__nv_bfloat162*)(yl+o)   = p;
    p.x=l[2]; p.y=l[3]; *(__nv_bfloat162*)(yl+o+2) = p;
}

// ===================== h = rmsnorm(2*m) -> bf16 hi/lo =====================
__global__ void __launch_bounds__(128) postnorm_kernel(const float* __restrict__ m,
                                                       __nv_bfloat16* __restrict__ hh,
                                                       __nv_bfloat16* __restrict__ hl){
    int row = blockIdx.x; int t = threadIdx.x;
    float4 mv = ((const float4*)(m + (size_t)row*DM))[t];
    float4 v = make_float4(2.f*mv.x, 2.f*mv.y, 2.f*mv.z, 2.f*mv.w);
    float ss = v.x*v.x + v.y*v.y + v.z*v.z + v.w*v.w;
    __shared__ float sh[4];
    #pragma unroll
    for (int o=16;o;o>>=1) ss += __shfl_xor_sync(0xffffffffu, ss, o);
    if ((t&31)==0) sh[t>>5] = ss;
    __syncthreads();
    float inv = rsqrtf((sh[0]+sh[1]+sh[2]+sh[3])*(1.f/DM) + EPSR);
    float o4[4] = {v.x*inv, v.y*inv, v.z*inv, v.w*inv};
    __nv_bfloat16 h[4], l[4];
    #pragma unroll
    for (int i=0;i<4;i++) split_bf16(o4[i], h[i], l[i]);
    size_t o = (size_t)row*DM + t*4;
    __nv_bfloat162 p;
    p.x=h[0]; p.y=h[1]; *(__nv_bfloat162*)(hh+o)   = p;
    p.x=h[2]; p.y=h[3]; *(__nv_bfloat162*)(hh+o+2) = p;
    p.x=l[0]; p.y=l[1]; *(__nv_bfloat162*)(hl+o)   = p;
    p.x=l[2]; p.y=l[3]; *(__nv_bfloat162*)(hl+o+2) = p;
}

extern "C" void kernel_launch(void* const* d_in, const int* in_sizes, int n_in,
                              void* d_out, int out_size){
    const float* x      = (const float*)d_in[0];
    const float* mask   = (const float*)d_in[1];
    const float* W_in   = (const float*)d_in[2];
    const float* conv_w = (const float*)d_in[3];
    const float* conv_b = (const float*)d_in[4];
    const float* dt_bias= (const float*)d_in[5];
    const float* A_log  = (const float*)d_in[6];
    const float* Dv     = (const float*)d_in[7];
    const float* norm_w = (const float*)d_in[8];
    const float* W_out  = (const float*)d_in[9];
    const float* W1     = (const float*)d_in[10];
    const float* b1     = (const float*)d_in[11];
    const float* W2     = (const float*)d_in[12];
    const float* b2     = (const float*)d_in[13];

    float* out_x  = (float*)d_out;
    float* out_m  = out_x  + (size_t)NBL*DM;
    float* out_dt = out_m  + (size_t)NBL*DM;
    float* out_z  = out_dt + (size_t)NBL*NH;

    float *pxraw;
    __nv_bfloat16 *puh,*pul,*py2h,*py2l,*phh,*phl,*pffh,*pffl;
    __nv_bfloat16 *pwih,*pwil,*pwoh,*pwol,*pw1h,*pw1l,*pw2h,*pw2l;
    cudaGetSymbolAddress((void**)&pxraw, g_xraw);
    cudaGetSymbolAddress((void**)&puh,  g_uh);  cudaGetSymbolAddress((void**)&pul,  g_ul);
    cudaGetSymbolAddress((void**)&py2h, g_y2h); cudaGetSymbolAddress((void**)&py2l, g_y2l);
    cudaGetSymbolAddress((void**)&phh,  g_hh);  cudaGetSymbolAddress((void**)&phl,  g_hl);
    cudaGetSymbolAddress((void**)&pffh, g_ffh); cudaGetSymbolAddress((void**)&pffl, g_ffl);
    cudaGetSymbolAddress((void**)&pwih, g_wih); cudaGetSymbolAddress((void**)&pwil, g_wil);
    cudaGetSymbolAddress((void**)&pwoh, g_woh); cudaGetSymbolAddress((void**)&pwol, g_wol);
    cudaGetSymbolAddress((void**)&pw1h, g_w1h); cudaGetSymbolAddress((void**)&pw1l, g_w1l);
    cudaGetSymbolAddress((void**)&pw2h, g_w2h); cudaGetSymbolAddress((void**)&pw2l, g_w2l);

    cudaFuncSetAttribute(mma_gemm<0>, cudaFuncAttributeMaxDynamicSharedMemorySize, GSMEM_BYTES);
    cudaFuncSetAttribute(mma_gemm<1>, cudaFuncAttributeMaxDynamicSharedMemorySize, GSMEM_BYTES);
    cudaFuncSetAttribute(mma_gemm<2>, cudaFuncAttributeMaxDynamicSharedMemorySize, GSMEM_BYTES);
    cudaFuncSetAttribute(mma_gemm<3>, cudaFuncAttributeMaxDynamicSharedMemorySize, GSMEM_BYTES);

    dim3 wb(32,8);
    wconv_kernel<<<dim3((DPROJ+31)/32, DM/32),   wb>>>(W_in,  pwih, pwil, DM,  DPROJ);
    wconv_kernel<<<dim3((DM+31)/32,    DIN/32),  wb>>>(W_out, pwoh, pwol, DIN, DM);
    wconv_kernel<<<dim3((DFF+31)/32,   DM/32),   wb>>>(W1,    pw1h, pw1l, DM,  DFF);
    wconv_kernel<<<dim3((DM+31)/32,    DFF/32),  wb>>>(W2,    pw2h, pw2l, DFF, DM);

    // 1) pre-norm -> bf16 split
    prenorm_kernel<<<NBL,128>>>(x, mask, puh, pul);
    // 2) in-projection, fused epilogue: z -> out_z, xBC -> g_xraw, dt -> out_dt
    mma_gemm<3><<<dim3((DPROJ+127)/128, NBL/128), 256, GSMEM_BYTES>>>(
        puh, pul, pwih, pwil, DPROJ, DM, nullptr, nullptr, nullptr, nullptr, nullptr,
        out_z, pxraw, out_dt, dt_bias);
    // 3) conv + silu + mask
    conv_kernel<<<(int)(((long)NBL*CONVD + 255)/256), 256>>>(conv_w, conv_b, mask);
    // 4) zero y
    zero_y_kernel<<<(NBL*DIN/4 + 255)/256, 256>>>();
    // 5) bidirectional scan
    scan_kernel<<<dim3(2,NH,BATCH), 128>>>(out_dt, A_log, Dv);
    // 6) gated rmsnorm -> bf16 split
    gatednorm_kernel<<<NBL,256>>>(out_z, norm_w, py2h, py2l);
    // 7) out projection -> m
    mma_gemm<0><<<dim3(DM/128, NBL/128), 256, GSMEM_BYTES>>>(
        py2h, py2l, pwoh, pwol, DM, DIN, out_m, nullptr, nullptr, nullptr, nullptr,
        nullptr, nullptr, nullptr, nullptr);
    // 8) h = rmsnorm(2m)
    postnorm_kernel<<<NBL,128>>>(out_m, phh, phl);
    // 9) FFN up
    mma_gemm<1><<<dim3(DFF/128, NBL/128), 256, GSMEM_BYTES>>>(
        phh, phl, pw1h, pw1l, DFF, DM, nullptr, b1, nullptr, pffh, pffl,
        nullptr, nullptr, nullptr, nullptr);
    // 10) FFN down + residual
    mma_gemm<2><<<dim3(DM/128, NBL/128), 256, GSMEM_BYTES>>>(
        pffh, pffl, pw2h, pw2l, DM, DFF, out_x, b2, out_m, nullptr, nullptr,
        nullptr, nullptr, nullptr, nullptr);
}